// round 15
// baseline (speedup 1.0000x reference)
#include <cuda_runtime.h>
#include <cuda_bf16.h>
#include <cuda_fp16.h>
#include <cstdint>

// ---------------------------------------------------------------------------
// Problem constants
// ---------------------------------------------------------------------------
static constexpr int NNODE = 20000;
static constexpr int EMAX  = 640000;
static constexpr int ETOT  = EMAX + NNODE;
static constexpr int INCH  = 256;
static constexpr int D1    = 128;            // conv1 out (8 heads x 16)
static constexpr int D2    = 256;            // conv2 out (1 head x 256)
static constexpr float NEG = 0.2f;
static constexpr int NBZ   = (NNODE + 255) / 256;   // 79 zero blocks
static constexpr int NSCAN = 20;                    // scan blocks (1024 nodes each)
static constexpr int NAGG2 = NNODE * 32 / 256;      // 2500 agg2 blocks

// ---------------------------------------------------------------------------
// Scratch (__device__ globals; no allocation allowed)
// ---------------------------------------------------------------------------
__device__ __nv_bfloat16 g_xh  [NNODE * INCH];   // gnn_x bf16 (GEMM1 A)
__device__ __nv_bfloat16 g_w1b [2 * D1 * INCH];  // [Wl1^T ; Wr1^T] bf16
__device__ __nv_bfloat16 g_w2b [2 * D2 * D1];    // [Wl2^T ; Wr2^T] bf16
__device__ uint8_t       g_xl1f8[NNODE * D1];    // conv1 xl (e4m3, gathered)
__device__ float         g_xr1 [NNODE * D1];     // conv1 xr (fp32)
__device__ __nv_bfloat16 g_x1h [NNODE * D1];     // relu(conv1 out) bf16
__device__ uint8_t       g_xl2f8[NNODE * D2];    // conv2 xl (e4m3, gathered)
__device__ float         g_xr2 [NNODE * D2];     // conv2 xr (fp32)
__device__ float         g_x2  [NNODE * D2];     // conv2 out (fp32)
__device__ float         g_logv[8192];           // vanilla part of classifier
__device__ int   g_counts[NNODE];
__device__ int   g_rank  [EMAX];                 // rank of edge within its dst
__device__ int   g_rowptr[NNODE + 1];
__device__ int   g_csr[ETOT];
__device__ int   g_bsum[32];
__device__ int   g_bflag[32];
__device__ int   g_flag;
__device__ int   g_zerodone;   // pre: zero-blocks done counter (reset in scan blk 0)
__device__ int   g_scancnt;    // launch C: scan blocks done (reset in pre)
__device__ int   g_aggdone;    // launch E: agg2 blocks done (reset in pre)

static inline int ceil_div(int a, int b) { return (a + b - 1) / b; }

// ---------------------------------------------------------------------------
// FP8 (e4m3) pack/unpack — baseline PTX since sm_89, OK on plain sm_103.
// ---------------------------------------------------------------------------
__device__ __forceinline__ uint16_t pack_e4m3(float hi, float lo) {
    uint16_t r;
    asm("cvt.rn.satfinite.e4m3x2.f32 %0, %1, %2;" : "=h"(r) : "f"(hi), "f"(lo));
    return r;
}
__device__ __forceinline__ float2 unpack_e4m3(uint16_t v) {
    uint32_t h2;
    asm("cvt.rn.f16x2.e4m3x2 %0, %1;" : "=r"(h2) : "h"(v));
    return __half22float2(*(__half2*)&h2);
}

// ---------------------------------------------------------------------------
// Launch 1: fused init + pre.
// Blocks: [zero NBZ][convX nbX][convW nbW][count nbC (gated)][detect nbD]
// ---------------------------------------------------------------------------
__global__ void __launch_bounds__(256)
pre_kernel(const float* __restrict__ x, __nv_bfloat16* __restrict__ xh,
           const float* __restrict__ Wl1, const float* __restrict__ Wr1,
           const float* __restrict__ Wl2, const float* __restrict__ Wr2,
           __nv_bfloat16* __restrict__ w1b, __nv_bfloat16* __restrict__ w2b,
           const int* __restrict__ dst, int E,
           const void* a1p, const void* a2p, int B,
           int nbX, int nbW, int nbC) {
    int bx = blockIdx.x, tid = threadIdx.x;
    if (bx < NBZ) {
        int i = bx * 256 + tid;
        if (i < NNODE) g_counts[i] = 0;
        if (bx == 0) {
            if (tid < 32) { g_bflag[tid] = 0; g_bsum[tid] = 0; }
            if (tid == 32) g_flag = 0;
            if (tid == 33) g_scancnt = 0;
            if (tid == 34) g_aggdone = 0;
        }
        __threadfence();
        __syncthreads();
        if (tid == 0) atomicAdd(&g_zerodone, 1);
    } else if (bx < NBZ + nbX) {
        int i = (bx - NBZ) * 256 + tid;
        constexpr int n4 = NNODE * INCH / 4;
        if (i < n4) {
            float4 v = ((const float4*)x)[i];
            uint2 p;
            *(__nv_bfloat162*)&p.x = __floats2bfloat162_rn(v.x, v.y);
            *(__nv_bfloat162*)&p.y = __floats2bfloat162_rn(v.z, v.w);
            ((uint2*)xh)[i] = p;
        }
    } else if (bx < NBZ + nbX + nbW) {
        int idx = (bx - NBZ - nbX) * 256 + tid;
        if (idx < 4 * 32768) {
            int z = idx >> 15, local = idx & 32767;
            const float* W = (z == 0) ? Wl1 : (z == 1) ? Wr1 : (z == 2) ? Wl2 : Wr2;
            __nv_bfloat16* o = (z == 0) ? w1b : (z == 1) ? (w1b + 32768)
                              : (z == 2) ? w2b : (w2b + 32768);
            int K = (z < 2) ? INCH : D1;
            int N = (z < 2) ? D1 : D2;
            int n = local / K, k = local % K;
            o[local] = __float2bfloat16(W[k * N + n]);
        }
    } else if (bx < NBZ + nbX + nbW + nbC) {
        if (tid == 0) { while (atomicAdd(&g_zerodone, 0) < NBZ) { } }
        __syncthreads();
        int e = (bx - NBZ - nbX - nbW) * 256 + tid;
        if (e < E) g_rank[e] = atomicAdd(&g_counts[dst[e]], 1);
    } else {
        int i = (bx - NBZ - nbX - nbW - nbC) * 256 + tid;
        if (i < B / 2) {
            long long v1 = ((const long long*)a1p)[i];
            long long v2 = ((const long long*)a2p)[i];
            if (v1 < 0 || v1 >= NNODE || v2 < 0 || v2 >= NNODE) g_flag = 1;
        }
    }
}

// ---------------------------------------------------------------------------
// 4-stage cp.async bf16 HMMA GEMM body with ldmatrix fragment loads.
// xl output written as FP8 (e4m3); xr output fp32.
// ---------------------------------------------------------------------------
template<int KD, int ND>
__device__ __forceinline__ void gemm_body(
    int rowTile, int slab,
    const __nv_bfloat16* __restrict__ A,
    const __nv_bfloat16* __restrict__ Wt,
    uint8_t* __restrict__ outLf8,
    float* __restrict__ outRf,
    char* smem)
{
    constexpr int STR    = 40;
    constexpr int NT     = KD / 32;
    constexpr int ABYTES = 128 * STR * 2;
    constexpr int SBYTES = 2 * ABYTES;
    constexpr int NSTAGE = 4;

    int tid = threadIdx.x, lane = tid & 31, wid = tid >> 5;
    int warpRow = wid >> 2, warpCol = wid & 3;
    int g = lane >> 2, t4 = lane & 3;
    int base = rowTile * 128;
    int slabBase = slab * 128;

    uint32_t sbase;
    asm("{ .reg .u64 t; cvta.to.shared.u64 t, %1; cvt.u32.u64 %0, t; }"
        : "=r"(sbase) : "l"(smem));

    int am = lane >> 3, ari = lane & 7;
    int bm = (lane >> 3) & 1, bri = lane & 7;
    uint32_t aoff[4], boff[4];
#pragma unroll
    for (int ma = 0; ma < 4; ma++)
        aoff[ma] = ((warpRow * 64 + ma * 16 + (am & 1) * 8 + ari) * STR + (am >> 1) * 8) * 2;
#pragma unroll
    for (int na = 0; na < 4; na++)
        boff[na] = ((warpCol * 32 + na * 8 + bri) * STR + bm * 8) * 2;

    float acc[4][4][4];
#pragma unroll
    for (int i = 0; i < 4; i++)
#pragma unroll
        for (int j = 0; j < 4; j++)
#pragma unroll
            for (int q = 0; q < 4; q++) acc[i][j][q] = 0.f;

    auto issue = [&](int s, int kt) {
#pragma unroll
        for (int it = 0; it < 2; it++) {
            int chunk = tid + it * 256;
            int r = chunk >> 2, c4 = chunk & 3;
            int gr = base + r;
            int grs = (gr < NNODE) ? gr : 0;
            uint32_t da = sbase + s * SBYTES + (r * STR + c4 * 8) * 2;
            const void* sa = &A[(size_t)grs * KD + kt * 32 + c4 * 8];
            int sz = (gr < NNODE) ? 16 : 0;
            asm volatile("cp.async.cg.shared.global [%0], [%1], 16, %2;"
                         :: "r"(da), "l"(sa), "r"(sz));
            uint32_t db = sbase + s * SBYTES + ABYTES + (r * STR + c4 * 8) * 2;
            const void* sb = &Wt[(size_t)(slabBase + r) * KD + kt * 32 + c4 * 8];
            asm volatile("cp.async.cg.shared.global [%0], [%1], 16;"
                         :: "r"(db), "l"(sb));
        }
        asm volatile("cp.async.commit_group;" ::: "memory");
    };

#pragma unroll
    for (int s = 0; s < NSTAGE - 1; s++)
        if (s < NT) issue(s, s); else asm volatile("cp.async.commit_group;" ::: "memory");

    for (int kt = 0; kt < NT; kt++) {
        asm volatile("cp.async.wait_group %0;" :: "n"(NSTAGE - 2) : "memory");
        __syncthreads();
        if (kt + NSTAGE - 1 < NT) issue((kt + NSTAGE - 1) % NSTAGE, kt + NSTAGE - 1);
        else asm volatile("cp.async.commit_group;" ::: "memory");

        uint32_t sA = sbase + (kt % NSTAGE) * SBYTES;
        uint32_t sB = sA + ABYTES;
#pragma unroll
        for (int kc = 0; kc < 2; kc++) {
            uint32_t a[4][4], b[4][2];
#pragma unroll
            for (int ma = 0; ma < 4; ma++) {
                asm volatile("ldmatrix.sync.aligned.m8n8.x4.shared.b16 "
                             "{%0, %1, %2, %3}, [%4];"
                             : "=r"(a[ma][0]), "=r"(a[ma][1]),
                               "=r"(a[ma][2]), "=r"(a[ma][3])
                             : "r"(sA + aoff[ma] + kc * 32));
            }
#pragma unroll
            for (int na = 0; na < 4; na++) {
                asm volatile("ldmatrix.sync.aligned.m8n8.x2.shared.b16 "
                             "{%0, %1}, [%2];"
                             : "=r"(b[na][0]), "=r"(b[na][1])
                             : "r"(sB + boff[na] + kc * 32));
            }
#pragma unroll
            for (int ma = 0; ma < 4; ma++)
#pragma unroll
                for (int na = 0; na < 4; na++) {
                    asm volatile(
                        "mma.sync.aligned.m16n8k16.row.col.f32.bf16.bf16.f32 "
                        "{%0, %1, %2, %3}, {%4, %5, %6, %7}, {%8, %9}, {%0, %1, %2, %3};"
                        : "+f"(acc[ma][na][0]), "+f"(acc[ma][na][1]),
                          "+f"(acc[ma][na][2]), "+f"(acc[ma][na][3])
                        : "r"(a[ma][0]), "r"(a[ma][1]), "r"(a[ma][2]), "r"(a[ma][3]),
                          "r"(b[na][0]), "r"(b[na][1]));
                }
        }
        __syncthreads();
    }

    bool isL = slabBase < ND;
    int colSlab = isL ? slabBase : (slabBase - ND);
#pragma unroll
    for (int ma = 0; ma < 4; ma++) {
        int r0 = base + warpRow * 64 + ma * 16 + g;
#pragma unroll
        for (int na = 0; na < 4; na++) {
            int col = colSlab + warpCol * 32 + na * 8 + 2 * t4;
            if (isL) {
                uint16_t e0 = pack_e4m3(acc[ma][na][1], acc[ma][na][0]);
                uint16_t e1 = pack_e4m3(acc[ma][na][3], acc[ma][na][2]);
                if (r0 < NNODE)     *(uint16_t*)&outLf8[(size_t)r0 * ND + col] = e0;
                if (r0 + 8 < NNODE) *(uint16_t*)&outLf8[(size_t)(r0 + 8) * ND + col] = e1;
            } else {
                if (r0 < NNODE)
                    *(float2*)&outRf[(size_t)r0 * ND + col] =
                        make_float2(acc[ma][na][0], acc[ma][na][1]);
                if (r0 + 8 < NNODE)
                    *(float2*)&outRf[(size_t)(r0 + 8) * ND + col] =
                        make_float2(acc[ma][na][2], acc[ma][na][3]);
            }
        }
    }
}

// ---------------------------------------------------------------------------
// Launch 2 (C): scan + GEMM1 + scatter(gated on scan) + vanilla classifier.
// Blocks: [scan NSCAN][gemm nGemm][scatter nScat][clsV].
// Scan: 20 blocks x 256 thr, 4 nodes/thread, chained via g_bsum/g_bflag.
// ---------------------------------------------------------------------------
__global__ void __launch_bounds__(256, 2)
c_kernel(const __nv_bfloat16* __restrict__ A,
         const __nv_bfloat16* __restrict__ Wt,
         uint8_t* __restrict__ outLf8, float* __restrict__ outRf,
         const int* __restrict__ src, const int* __restrict__ dst,
         int E, int Etot, int nGemm, int nScat,
         const float* __restrict__ vanilla,
         const void* a1p, const void* a2p,
         const float* __restrict__ Wc, int B) {
    extern __shared__ char smem[];
    int bx = blockIdx.x, tid = threadIdx.x;

    if (bx < NSCAN) {
        __shared__ int sh[256];
        __shared__ int s_off;
        if (bx == 0 && tid == 0) g_zerodone = 0;   // reset for next sequence
        int base = bx * 1024 + tid * 4;
        int v0 = (base + 0 < NNODE) ? g_counts[base + 0] + 1 : 0;
        int v1 = (base + 1 < NNODE) ? g_counts[base + 1] + 1 : 0;
        int v2 = (base + 2 < NNODE) ? g_counts[base + 2] + 1 : 0;
        int v3 = (base + 3 < NNODE) ? g_counts[base + 3] + 1 : 0;
        int s4 = v0 + v1 + v2 + v3;
        sh[tid] = s4;
        __syncthreads();
        for (int off = 1; off < 256; off <<= 1) {
            int t = (tid >= off) ? sh[tid - off] : 0;
            __syncthreads();
            sh[tid] += t;
            __syncthreads();
        }
        int incl = sh[tid];
        if (tid == 0) {
            int off = 0;
            if (bx > 0) {
                while (atomicAdd(&g_bflag[bx - 1], 0) == 0) { }
                off = atomicAdd(&g_bsum[bx - 1], 0);
            }
            s_off = off;
            atomicExch(&g_bsum[bx], off + sh[255]);
            __threadfence();
            atomicExch(&g_bflag[bx], 1);
        }
        __syncthreads();
        int r = s_off + incl - s4;
        if (base + 0 < NNODE) { r += v0; g_rowptr[base + 1] = r; }
        if (base + 1 < NNODE) { r += v1; g_rowptr[base + 2] = r; }
        if (base + 2 < NNODE) { r += v2; g_rowptr[base + 3] = r; }
        if (base + 3 < NNODE) { r += v3; g_rowptr[base + 4] = r; }
        if (bx == 0 && tid == 0) g_rowptr[0] = 0;
        __threadfence();
        __syncthreads();
        if (tid == 0) atomicAdd(&g_scancnt, 1);
    } else if (bx < NSCAN + nGemm) {
        int gb = bx - NSCAN;
        gemm_body<INCH, D1>(gb >> 1, gb & 1, A, Wt, outLf8, outRf, smem);
    } else if (bx < NSCAN + nGemm + nScat) {
        if (tid == 0) { while (atomicAdd(&g_scancnt, 0) < NSCAN) { } }
        __syncthreads();
        int b = bx - NSCAN - nGemm;
#pragma unroll
        for (int q = 0; q < 4; q++) {
            int e = (b * 4 + q) * 256 + tid;
            if (e < Etot) {
                if (e < E) {
                    int d = dst[e];
                    g_csr[g_rowptr[d] + g_rank[e]] = src[e];
                } else {
                    int i = e - E;
                    g_csr[g_rowptr[i] + g_counts[i]] = i;
                }
            }
        }
    } else {
        int w = ((bx - NSCAN - nGemm - nScat) * 256 + tid) >> 5;
        int lane = tid & 31;
        if (w >= B) return;
        long long a1, a2;
        if (g_flag) { a1 = ((const int*)a1p)[w]; a2 = ((const int*)a2p)[w]; }
        else        { a1 = ((const long long*)a1p)[w]; a2 = ((const long long*)a2p)[w]; }
        const float* v1 = vanilla + a1 * INCH;
        const float* v2 = vanilla + a2 * INCH;
        float acc = 0.f;
#pragma unroll
        for (int j = lane; j < 256; j += 32) {
            acc = fmaf(v1[j], Wc[j],       acc);
            acc = fmaf(v2[j], Wc[256 + j], acc);
        }
#pragma unroll
        for (int off = 16; off > 0; off >>= 1) acc += __shfl_xor_sync(0xffffffffu, acc, off);
        if (lane == 0) g_logv[w] = acc;
    }
}

// ---------------------------------------------------------------------------
// Launch 3: conv1 aggregation (FP8 gathers; 2-edge pipeline).
// ---------------------------------------------------------------------------
__global__ __launch_bounds__(256)
void agg_conv1_kernel(const float* __restrict__ att, const float* __restrict__ bias) {
    int w = (blockIdx.x * blockDim.x + threadIdx.x) >> 5;
    int lane = threadIdx.x & 31;
    if (w >= NNODE) return;
    int c0 = lane * 4;

    float4 xrv = *(const float4*)&g_xr1[w * D1 + c0];
    float4 atv = *(const float4*)&att[c0];

    float a0 = 0.f, a1 = 0.f, a2 = 0.f, a3 = 0.f, dsum = 0.f;
    int beg = g_rowptr[w], end = g_rowptr[w + 1];
    int last = end - 1;

    int s0 = g_csr[beg];
    int s1 = g_csr[beg + 1 <= last ? beg + 1 : last];
    uint32_t c0v = *(const uint32_t*)&g_xl1f8[s0 * D1 + c0];
    uint32_t c1v = *(const uint32_t*)&g_xl1f8[s1 * D1 + c0];

    auto body = [&](uint32_t v) {
        float2 f01 = unpack_e4m3((uint16_t)(v & 0xffffu));
        float2 f23 = unpack_e4m3((uint16_t)(v >> 16));
        float u0 = f01.x + xrv.x; u0 = u0 > 0.f ? u0 : NEG * u0;
        float u1 = f01.y + xrv.y; u1 = u1 > 0.f ? u1 : NEG * u1;
        float u2 = f23.x + xrv.z; u2 = u2 > 0.f ? u2 : NEG * u2;
        float u3 = f23.y + xrv.w; u3 = u3 > 0.f ? u3 : NEG * u3;
        float p = u0 * atv.x + u1 * atv.y + u2 * atv.z + u3 * atv.w;
        p += __shfl_xor_sync(0xffffffffu, p, 1);
        p += __shfl_xor_sync(0xffffffffu, p, 2);
        float ex = __expf(p);
        dsum += ex;
        a0 = fmaf(ex, f01.x, a0);
        a1 = fmaf(ex, f01.y, a1);
        a2 = fmaf(ex, f23.x, a2);
        a3 = fmaf(ex, f23.y, a3);
    };

    for (int i = beg; i < end; i += 2) {
        int j0 = i + 2 <= last ? i + 2 : last;
        int j1 = i + 3 <= last ? i + 3 : last;
        int t0 = g_csr[j0], t1 = g_csr[j1];
        uint32_t n0 = *(const uint32_t*)&g_xl1f8[t0 * D1 + c0];
        uint32_t n1 = *(const uint32_t*)&g_xl1f8[t1 * D1 + c0];
        body(c0v);
        if (i + 1 < end) body(c1v);
        c0v = n0;
        c1v = n1;
    }
    float inv = 1.f / dsum;
    float4 bv = *(const float4*)&bias[c0];
    float o0 = fmaxf(fmaf(a0, inv, bv.x), 0.f);
    float o1 = fmaxf(fmaf(a1, inv, bv.y), 0.f);
    float o2 = fmaxf(fmaf(a2, inv, bv.z), 0.f);
    float o3 = fmaxf(fmaf(a3, inv, bv.w), 0.f);
    uint2 oh;
    *(__nv_bfloat162*)&oh.x = __floats2bfloat162_rn(o0, o1);
    *(__nv_bfloat162*)&oh.y = __floats2bfloat162_rn(o2, o3);
    *(uint2*)&g_x1h[w * D1 + c0] = oh;
}

// ---------------------------------------------------------------------------
// Launch 4: GEMM2.
// ---------------------------------------------------------------------------
__global__ void __launch_bounds__(256, 2)
gemm2_kernel(const __nv_bfloat16* __restrict__ A,
             const __nv_bfloat16* __restrict__ Wt,
             uint8_t* __restrict__ outLf8, float* __restrict__ outRf) {
    extern __shared__ char smem[];
    gemm_body<D1, D2>(blockIdx.x >> 2, blockIdx.x & 3, A, Wt, outLf8, outRf, smem);
}

// ---------------------------------------------------------------------------
// Launch 5 (E): agg2 + classifier tail (gated on agg2 completion).
// Blocks: [agg2 NAGG2][classify].
// ---------------------------------------------------------------------------
__global__ void __launch_bounds__(256)
e_kernel(const float* __restrict__ att, const float* __restrict__ bias,
         const void* a1p, const void* a2p,
         const float* __restrict__ Wc, const float* __restrict__ bc,
         float* __restrict__ out, int B) {
    int bx = blockIdx.x, tid = threadIdx.x;
    int lane = tid & 31;

    if (bx < NAGG2) {
        int w = (bx * 256 + tid) >> 5;
        int c0 = lane * 8;

        float4 xra = *(const float4*)&g_xr2[w * D2 + c0];
        float4 xrb = *(const float4*)&g_xr2[w * D2 + c0 + 4];
        float4 ata = *(const float4*)&att[c0];
        float4 atb = *(const float4*)&att[c0 + 4];
        float xr[8] = {xra.x, xra.y, xra.z, xra.w, xrb.x, xrb.y, xrb.z, xrb.w};
        float at[8] = {ata.x, ata.y, ata.z, ata.w, atb.x, atb.y, atb.z, atb.w};

        float acc[8] = {0.f, 0.f, 0.f, 0.f, 0.f, 0.f, 0.f, 0.f};
        float dsum = 0.f;
        int beg = g_rowptr[w], end = g_rowptr[w + 1];
        int last = end - 1;

        int s0 = g_csr[beg];
        int s1 = g_csr[beg + 1 <= last ? beg + 1 : last];
        uint2 c0v = *(const uint2*)&g_xl2f8[s0 * D2 + c0];
        uint2 c1v = *(const uint2*)&g_xl2f8[s1 * D2 + c0];

        auto body = [&](uint2 cv) {
            float xl[8];
            float2 f;
            f = unpack_e4m3((uint16_t)(cv.x & 0xffffu)); xl[0] = f.x; xl[1] = f.y;
            f = unpack_e4m3((uint16_t)(cv.x >> 16));     xl[2] = f.x; xl[3] = f.y;
            f = unpack_e4m3((uint16_t)(cv.y & 0xffffu)); xl[4] = f.x; xl[5] = f.y;
            f = unpack_e4m3((uint16_t)(cv.y >> 16));     xl[6] = f.x; xl[7] = f.y;
            float p = 0.f;
#pragma unroll
            for (int j = 0; j < 8; j++) {
                float t = xl[j] + xr[j];
                t = t > 0.f ? t : NEG * t;
                p = fmaf(t, at[j], p);
            }
#pragma unroll
            for (int off = 16; off > 0; off >>= 1) p += __shfl_xor_sync(0xffffffffu, p, off);
            float ex = __expf(p);
            dsum += ex;
#pragma unroll
            for (int j = 0; j < 8; j++) acc[j] = fmaf(ex, xl[j], acc[j]);
        };

        for (int i = beg; i < end; i += 2) {
            int j0 = i + 2 <= last ? i + 2 : last;
            int j1 = i + 3 <= last ? i + 3 : last;
            int t0 = g_csr[j0], t1 = g_csr[j1];
            uint2 n0 = *(const uint2*)&g_xl2f8[t0 * D2 + c0];
            uint2 n1 = *(const uint2*)&g_xl2f8[t1 * D2 + c0];
            body(c0v);
            if (i + 1 < end) body(c1v);
            c0v = n0;
            c1v = n1;
        }
        float inv = 1.f / dsum;
        float4 ba = *(const float4*)&bias[c0];
        float4 bb = *(const float4*)&bias[c0 + 4];
        float4 oa, ob;
        oa.x = fmaf(acc[0], inv, ba.x);
        oa.y = fmaf(acc[1], inv, ba.y);
        oa.z = fmaf(acc[2], inv, ba.z);
        oa.w = fmaf(acc[3], inv, ba.w);
        ob.x = fmaf(acc[4], inv, bb.x);
        ob.y = fmaf(acc[5], inv, bb.y);
        ob.z = fmaf(acc[6], inv, bb.z);
        ob.w = fmaf(acc[7], inv, bb.w);
        *(float4*)&g_x2[w * D2 + c0] = oa;
        *(float4*)&g_x2[w * D2 + c0 + 4] = ob;

        __threadfence();
        __syncthreads();
        if (tid == 0) atomicAdd(&g_aggdone, 1);
    } else {
        if (tid == 0) { while (atomicAdd(&g_aggdone, 0) < NAGG2) { } }
        __syncthreads();
        int w = ((bx - NAGG2) * 256 + tid) >> 5;
        if (w >= B) return;
        long long a1, a2;
        if (g_flag) { a1 = ((const int*)a1p)[w]; a2 = ((const int*)a2p)[w]; }
        else        { a1 = ((const long long*)a1p)[w]; a2 = ((const long long*)a2p)[w]; }

        const float* x1 = g_x2 + a1 * D2;
        const float* x2 = g_x2 + a2 * D2;

        float acc = 0.f;
#pragma unroll
        for (int j = lane; j < 256; j += 32) {
            acc = fmaf(x1[j], Wc[512 + j], acc);
            acc = fmaf(x2[j], Wc[768 + j], acc);
        }
#pragma unroll
        for (int off = 16; off > 0; off >>= 1) acc += __shfl_xor_sync(0xffffffffu, acc, off);
        if (lane == 0) out[w] = acc + g_logv[w] + bc[0];
    }
}

// ---------------------------------------------------------------------------
// Launch
// ---------------------------------------------------------------------------
extern "C" void kernel_launch(void* const* d_in, const int* in_sizes, int n_in,
                              void* d_out, int out_size) {
    const float* gnn_x   = (const float*)d_in[0];
    const float* vanilla = (const float*)d_in[1];
    const int*   e_src   = (const int*)d_in[2];
    const int*   e_dst   = (const int*)d_in[3];
    const void*  a1p     = d_in[4];
    const void*  a2p     = d_in[5];
    const float* Wl1     = (const float*)d_in[6];
    const float* Wr1     = (const float*)d_in[8];
    const float* att1    = (const float*)d_in[10];
    const float* bias1   = (const float*)d_in[11];
    const float* Wl2     = (const float*)d_in[12];
    const float* Wr2     = (const float*)d_in[14];
    const float* att2    = (const float*)d_in[16];
    const float* bias2   = (const float*)d_in[17];
    const float* Wc      = (const float*)d_in[18];
    const float* bc      = (const float*)d_in[19];

    const int E = in_sizes[2];
    const int Etot = E + NNODE;
    const int B = in_sizes[4];
    float* out = (float*)d_out;

    __nv_bfloat16 *p_xh, *p_w1b, *p_w2b, *p_x1h;
    uint8_t *p_xl1f8, *p_xl2f8;
    float *p_xr1, *p_xr2;
    cudaGetSymbolAddress((void**)&p_xh,    g_xh);
    cudaGetSymbolAddress((void**)&p_w1b,   g_w1b);
    cudaGetSymbolAddress((void**)&p_w2b,   g_w2b);
    cudaGetSymbolAddress((void**)&p_xl1f8, g_xl1f8);
    cudaGetSymbolAddress((void**)&p_xr1,   g_xr1);
    cudaGetSymbolAddress((void**)&p_x1h,   g_x1h);
    cudaGetSymbolAddress((void**)&p_xl2f8, g_xl2f8);
    cudaGetSymbolAddress((void**)&p_xr2,   g_xr2);

    constexpr int SMEM_GEMM = 4 * 2 * 128 * 40 * 2;   // 81920 B (4 stages)
    cudaFuncSetAttribute(c_kernel,
                         cudaFuncAttributeMaxDynamicSharedMemorySize, SMEM_GEMM);
    cudaFuncSetAttribute(gemm2_kernel,
                         cudaFuncAttributeMaxDynamicSharedMemorySize, SMEM_GEMM);

    // ---- 1. fused init + pre ----
    int nbX = ceil_div(NNODE * INCH / 4, 256);
    int nbW = ceil_div(4 * 32768, 256);
    int nbC = ceil_div(E, 256);
    int nbD = ceil_div(B / 2, 256);
    pre_kernel<<<NBZ + nbX + nbW + nbC + nbD, 256>>>(
        gnn_x, p_xh, Wl1, Wr1, Wl2, Wr2, p_w1b, p_w2b,
        e_dst, E, a1p, a2p, B, nbX, nbW, nbC);

    // ---- 2. scan + GEMM1 + scatter + vanilla-classifier ----
    int nGemm1 = 2 * ceil_div(NNODE, 128);           // 314
    int nScat  = ceil_div(Etot, 1024);
    int nClsV  = ceil_div(B * 32, 256);
    c_kernel<<<NSCAN + nGemm1 + nScat + nClsV, 256, SMEM_GEMM>>>(
        p_xh, p_w1b, p_xl1f8, p_xr1, e_src, e_dst, E, Etot, nGemm1, nScat,
        vanilla, a1p, a2p, Wc, B);

    // ---- 3. conv1 aggregation ----
    agg_conv1_kernel<<<ceil_div(NNODE * 32, 256), 256>>>(att1, bias1);

    // ---- 4. GEMM2 ----
    gemm2_kernel<<<4 * ceil_div(NNODE, 128), 256, SMEM_GEMM>>>(
        p_x1h, p_w2b, p_xl2f8, p_xr2);

    // ---- 5. conv2 aggregation + classifier tail ----
    e_kernel<<<NAGG2 + ceil_div(B * 32, 256), 256>>>(
        att2, bias2, a1p, a2p, Wc, bc, out, B);
}

// round 16
// speedup vs baseline: 1.0229x; 1.0229x over previous
#include <cuda_runtime.h>
#include <cuda_bf16.h>
#include <cuda_fp16.h>
#include <cstdint>

// ---------------------------------------------------------------------------
// Problem constants
// ---------------------------------------------------------------------------
static constexpr int NNODE = 20000;
static constexpr int EMAX  = 640000;
static constexpr int ETOT  = EMAX + NNODE;
static constexpr int INCH  = 256;
static constexpr int D1    = 128;            // conv1 out (8 heads x 16)
static constexpr int D2    = 256;            // conv2 out (1 head x 256)
static constexpr float NEG = 0.2f;
static constexpr int NAGG1 = NNODE * 32 / 256;      // 2500 agg1 blocks

// ---------------------------------------------------------------------------
// Scratch (__device__ globals; no allocation allowed)
// ---------------------------------------------------------------------------
__device__ __nv_bfloat16 g_xh  [NNODE * INCH];   // gnn_x bf16 (GEMM1 A)
__device__ __nv_bfloat16 g_w1b [2 * D1 * INCH];  // [Wl1^T ; Wr1^T] bf16
__device__ __nv_bfloat16 g_w2b [2 * D2 * D1];    // [Wl2^T ; Wr2^T] bf16
__device__ uint8_t       g_xl1f8[NNODE * D1];    // conv1 xl (e4m3, gathered)
__device__ float         g_xr1 [NNODE * D1];     // conv1 xr (fp32)
__device__ __nv_bfloat16 g_x1h [NNODE * D1];     // relu(conv1 out) bf16
__device__ uint8_t       g_xl2f8[NNODE * D2];    // conv2 xl (e4m3, gathered)
__device__ float         g_xr2 [NNODE * D2];     // conv2 xr (fp32)
__device__ float         g_x2  [NNODE * D2];     // conv2 out (fp32)
__device__ float         g_logv[8192];           // vanilla part of classifier
__device__ int   g_counts[NNODE];
__device__ int   g_rank  [EMAX];                 // rank of edge within its dst
__device__ int   g_rowptr[NNODE + 1];
__device__ int   g_csr[ETOT];
__device__ int   g_bsum[32];
__device__ int   g_bflag[32];
__device__ int   g_flag;

static inline int ceil_div(int a, int b) { return (a + b - 1) / b; }

// ---------------------------------------------------------------------------
// FP8 (e4m3) pack/unpack — baseline PTX since sm_89, OK on plain sm_103.
// ---------------------------------------------------------------------------
__device__ __forceinline__ uint16_t pack_e4m3(float hi, float lo) {
    uint16_t r;
    asm("cvt.rn.satfinite.e4m3x2.f32 %0, %1, %2;" : "=h"(r) : "f"(hi), "f"(lo));
    return r;
}
__device__ __forceinline__ float2 unpack_e4m3(uint16_t v) {
    uint32_t h2;
    asm("cvt.rn.f16x2.e4m3x2 %0, %1;" : "=r"(h2) : "h"(v));
    return __half22float2(*(__half2*)&h2);
}

// ---------------------------------------------------------------------------
// Init
// ---------------------------------------------------------------------------
__global__ void init_kernel() {
    int i = blockIdx.x * blockDim.x + threadIdx.x;
    if (i < NNODE) g_counts[i] = 0;
    if (i < 32) g_bflag[i] = 0;
    if (i == 0) g_flag = 0;
}

// ---------------------------------------------------------------------------
// Fused pre-pass: bf16 conversions + degree count (captures ranks) + detect.
// Weight transpose-convert uses COALESCED reads (consecutive n), strided writes.
// ---------------------------------------------------------------------------
__global__ void __launch_bounds__(256)
pre_kernel(const float* __restrict__ x, __nv_bfloat16* __restrict__ xh,
           const float* __restrict__ Wl1, const float* __restrict__ Wr1,
           const float* __restrict__ Wl2, const float* __restrict__ Wr2,
           __nv_bfloat16* __restrict__ w1b, __nv_bfloat16* __restrict__ w2b,
           const int* __restrict__ dst, int E,
           const void* a1p, const void* a2p, int B,
           int nbX, int nbW, int nbC) {
    int bx = blockIdx.x, tid = threadIdx.x;
    if (bx < nbX) {
        int i = bx * 256 + tid;
        constexpr int n4 = NNODE * INCH / 4;
        if (i < n4) {
            float4 v = ((const float4*)x)[i];
            uint2 p;
            *(__nv_bfloat162*)&p.x = __floats2bfloat162_rn(v.x, v.y);
            *(__nv_bfloat162*)&p.y = __floats2bfloat162_rn(v.z, v.w);
            ((uint2*)xh)[i] = p;
        }
    } else if (bx < nbX + nbW) {
        int idx = (bx - nbX) * 256 + tid;
        if (idx < 4 * 32768) {
            int z = idx >> 15, local = idx & 32767;
            const float* W = (z == 0) ? Wl1 : (z == 1) ? Wr1 : (z == 2) ? Wl2 : Wr2;
            __nv_bfloat16* o = (z == 0) ? w1b : (z == 1) ? (w1b + 32768)
                              : (z == 2) ? w2b : (w2b + 32768);
            int K = (z < 2) ? INCH : D1;
            int N = (z < 2) ? D1 : D2;
            int k = local / N, n = local % N;        // consecutive n -> coalesced read
            o[n * K + k] = __float2bfloat16(W[local]);
        }
    } else if (bx < nbX + nbW + nbC) {
        int e = (bx - nbX - nbW) * 256 + tid;
        if (e < E) g_rank[e] = atomicAdd(&g_counts[dst[e]], 1);
    } else {
        int i = (bx - nbX - nbW - nbC) * 256 + tid;
        if (i < B / 2) {
            long long v1 = ((const long long*)a1p)[i];
            long long v2 = ((const long long*)a2p)[i];
            if (v1 < 0 || v1 >= NNODE || v2 < 0 || v2 >= NNODE) g_flag = 1;
        }
    }
}

// ---------------------------------------------------------------------------
// Chained multi-block scan over (counts[i] + 1). 20 co-resident blocks,
// 256 threads x 4 nodes each (half the barrier rounds of the 1024-thr version).
// ---------------------------------------------------------------------------
__global__ void __launch_bounds__(256)
scan_chained_kernel() {
    __shared__ int sh[256];
    __shared__ int s_off;
    int tid = threadIdx.x, bx = blockIdx.x;
    int base = bx * 1024 + tid * 4;
    int v0 = (base + 0 < NNODE) ? g_counts[base + 0] + 1 : 0;
    int v1 = (base + 1 < NNODE) ? g_counts[base + 1] + 1 : 0;
    int v2 = (base + 2 < NNODE) ? g_counts[base + 2] + 1 : 0;
    int v3 = (base + 3 < NNODE) ? g_counts[base + 3] + 1 : 0;
    int s4 = v0 + v1 + v2 + v3;
    sh[tid] = s4;
    __syncthreads();
    for (int off = 1; off < 256; off <<= 1) {
        int t = (tid >= off) ? sh[tid - off] : 0;
        __syncthreads();
        sh[tid] += t;
        __syncthreads();
    }
    int incl = sh[tid];
    if (tid == 0) {
        int off = 0;
        if (bx > 0) {
            while (atomicAdd(&g_bflag[bx - 1], 0) == 0) { }
            off = atomicAdd(&g_bsum[bx - 1], 0);
        }
        s_off = off;
        atomicExch(&g_bsum[bx], off + sh[255]);
        __threadfence();
        atomicExch(&g_bflag[bx], 1);
    }
    __syncthreads();
    int r = s_off + incl - s4;
    if (base + 0 < NNODE) { r += v0; g_rowptr[base + 1] = r; }
    if (base + 1 < NNODE) { r += v1; g_rowptr[base + 2] = r; }
    if (base + 2 < NNODE) { r += v2; g_rowptr[base + 3] = r; }
    if (base + 3 < NNODE) { r += v3; g_rowptr[base + 4] = r; }
    if (bx == 0 && tid == 0) g_rowptr[0] = 0;
}

// ---------------------------------------------------------------------------
// 4-stage cp.async bf16 HMMA GEMM body with ldmatrix fragment loads.
// xl output written as FP8 (e4m3); xr output fp32.
// ---------------------------------------------------------------------------
template<int KD, int ND>
__device__ __forceinline__ void gemm_body(
    int rowTile, int slab,
    const __nv_bfloat16* __restrict__ A,
    const __nv_bfloat16* __restrict__ Wt,
    uint8_t* __restrict__ outLf8,
    float* __restrict__ outRf,
    char* smem)
{
    constexpr int STR    = 40;
    constexpr int NT     = KD / 32;
    constexpr int ABYTES = 128 * STR * 2;
    constexpr int SBYTES = 2 * ABYTES;
    constexpr int NSTAGE = 4;

    int tid = threadIdx.x, lane = tid & 31, wid = tid >> 5;
    int warpRow = wid >> 2, warpCol = wid & 3;
    int g = lane >> 2, t4 = lane & 3;
    int base = rowTile * 128;
    int slabBase = slab * 128;

    uint32_t sbase;
    asm("{ .reg .u64 t; cvta.to.shared.u64 t, %1; cvt.u32.u64 %0, t; }"
        : "=r"(sbase) : "l"(smem));

    int am = lane >> 3, ari = lane & 7;
    int bm = (lane >> 3) & 1, bri = lane & 7;
    uint32_t aoff[4], boff[4];
#pragma unroll
    for (int ma = 0; ma < 4; ma++)
        aoff[ma] = ((warpRow * 64 + ma * 16 + (am & 1) * 8 + ari) * STR + (am >> 1) * 8) * 2;
#pragma unroll
    for (int na = 0; na < 4; na++)
        boff[na] = ((warpCol * 32 + na * 8 + bri) * STR + bm * 8) * 2;

    float acc[4][4][4];
#pragma unroll
    for (int i = 0; i < 4; i++)
#pragma unroll
        for (int j = 0; j < 4; j++)
#pragma unroll
            for (int q = 0; q < 4; q++) acc[i][j][q] = 0.f;

    auto issue = [&](int s, int kt) {
#pragma unroll
        for (int it = 0; it < 2; it++) {
            int chunk = tid + it * 256;
            int r = chunk >> 2, c4 = chunk & 3;
            int gr = base + r;
            int grs = (gr < NNODE) ? gr : 0;
            uint32_t da = sbase + s * SBYTES + (r * STR + c4 * 8) * 2;
            const void* sa = &A[(size_t)grs * KD + kt * 32 + c4 * 8];
            int sz = (gr < NNODE) ? 16 : 0;
            asm volatile("cp.async.cg.shared.global [%0], [%1], 16, %2;"
                         :: "r"(da), "l"(sa), "r"(sz));
            uint32_t db = sbase + s * SBYTES + ABYTES + (r * STR + c4 * 8) * 2;
            const void* sb = &Wt[(size_t)(slabBase + r) * KD + kt * 32 + c4 * 8];
            asm volatile("cp.async.cg.shared.global [%0], [%1], 16;"
                         :: "r"(db), "l"(sb));
        }
        asm volatile("cp.async.commit_group;" ::: "memory");
    };

#pragma unroll
    for (int s = 0; s < NSTAGE - 1; s++)
        if (s < NT) issue(s, s); else asm volatile("cp.async.commit_group;" ::: "memory");

    for (int kt = 0; kt < NT; kt++) {
        asm volatile("cp.async.wait_group %0;" :: "n"(NSTAGE - 2) : "memory");
        __syncthreads();
        if (kt + NSTAGE - 1 < NT) issue((kt + NSTAGE - 1) % NSTAGE, kt + NSTAGE - 1);
        else asm volatile("cp.async.commit_group;" ::: "memory");

        uint32_t sA = sbase + (kt % NSTAGE) * SBYTES;
        uint32_t sB = sA + ABYTES;
#pragma unroll
        for (int kc = 0; kc < 2; kc++) {
            uint32_t a[4][4], b[4][2];
#pragma unroll
            for (int ma = 0; ma < 4; ma++) {
                asm volatile("ldmatrix.sync.aligned.m8n8.x4.shared.b16 "
                             "{%0, %1, %2, %3}, [%4];"
                             : "=r"(a[ma][0]), "=r"(a[ma][1]),
                               "=r"(a[ma][2]), "=r"(a[ma][3])
                             : "r"(sA + aoff[ma] + kc * 32));
            }
#pragma unroll
            for (int na = 0; na < 4; na++) {
                asm volatile("ldmatrix.sync.aligned.m8n8.x2.shared.b16 "
                             "{%0, %1}, [%2];"
                             : "=r"(b[na][0]), "=r"(b[na][1])
                             : "r"(sB + boff[na] + kc * 32));
            }
#pragma unroll
            for (int ma = 0; ma < 4; ma++)
#pragma unroll
                for (int na = 0; na < 4; na++) {
                    asm volatile(
                        "mma.sync.aligned.m16n8k16.row.col.f32.bf16.bf16.f32 "
                        "{%0, %1, %2, %3}, {%4, %5, %6, %7}, {%8, %9}, {%0, %1, %2, %3};"
                        : "+f"(acc[ma][na][0]), "+f"(acc[ma][na][1]),
                          "+f"(acc[ma][na][2]), "+f"(acc[ma][na][3])
                        : "r"(a[ma][0]), "r"(a[ma][1]), "r"(a[ma][2]), "r"(a[ma][3]),
                          "r"(b[na][0]), "r"(b[na][1]));
                }
        }
        __syncthreads();
    }

    bool isL = slabBase < ND;
    int colSlab = isL ? slabBase : (slabBase - ND);
#pragma unroll
    for (int ma = 0; ma < 4; ma++) {
        int r0 = base + warpRow * 64 + ma * 16 + g;
#pragma unroll
        for (int na = 0; na < 4; na++) {
            int col = colSlab + warpCol * 32 + na * 8 + 2 * t4;
            if (isL) {
                uint16_t e0 = pack_e4m3(acc[ma][na][1], acc[ma][na][0]);
                uint16_t e1 = pack_e4m3(acc[ma][na][3], acc[ma][na][2]);
                if (r0 < NNODE)     *(uint16_t*)&outLf8[(size_t)r0 * ND + col] = e0;
                if (r0 + 8 < NNODE) *(uint16_t*)&outLf8[(size_t)(r0 + 8) * ND + col] = e1;
            } else {
                if (r0 < NNODE)
                    *(float2*)&outRf[(size_t)r0 * ND + col] =
                        make_float2(acc[ma][na][0], acc[ma][na][1]);
                if (r0 + 8 < NNODE)
                    *(float2*)&outRf[(size_t)(r0 + 8) * ND + col] =
                        make_float2(acc[ma][na][2], acc[ma][na][3]);
            }
        }
    }
}

// ---------------------------------------------------------------------------
// Fused GEMM1 + atomic-free scatter (ranks precomputed).
// ---------------------------------------------------------------------------
__global__ void __launch_bounds__(256, 2)
g1_scatter_kernel(const __nv_bfloat16* __restrict__ A,
                  const __nv_bfloat16* __restrict__ Wt,
                  uint8_t* __restrict__ outLf8, float* __restrict__ outRf,
                  const int* __restrict__ src, const int* __restrict__ dst,
                  int E, int Etot, int nGemm) {
    extern __shared__ char smem[];
    if ((int)blockIdx.x < nGemm) {
        gemm_body<INCH, D1>(blockIdx.x >> 1, blockIdx.x & 1, A, Wt, outLf8, outRf, smem);
    } else {
        int b = blockIdx.x - nGemm;
#pragma unroll
        for (int q = 0; q < 4; q++) {
            int e = (b * 4 + q) * 256 + threadIdx.x;
            if (e < Etot) {
                if (e < E) {
                    int d = dst[e];
                    g_csr[g_rowptr[d] + g_rank[e]] = src[e];
                } else {
                    int i = e - E;
                    g_csr[g_rowptr[i] + g_counts[i]] = i;
                }
            }
        }
    }
}

__global__ void __launch_bounds__(256, 2)
gemm2_kernel(const __nv_bfloat16* __restrict__ A,
             const __nv_bfloat16* __restrict__ Wt,
             uint8_t* __restrict__ outLf8, float* __restrict__ outRf) {
    extern __shared__ char smem[];
    gemm_body<D1, D2>(blockIdx.x >> 2, blockIdx.x & 3, A, Wt, outLf8, outRf, smem);
}

// ---------------------------------------------------------------------------
// Conv1 aggregation + vanilla-classifier partial (independent, same footprint).
// Blocks [0, NAGG1): agg1.  Rest: clsV at full occupancy.
// ---------------------------------------------------------------------------
__global__ __launch_bounds__(256)
void agg1_clsv_kernel(const float* __restrict__ att, const float* __restrict__ bias,
                      const float* __restrict__ vanilla,
                      const void* a1p, const void* a2p,
                      const float* __restrict__ Wc, int B) {
    int bx = blockIdx.x, tid = threadIdx.x;
    int lane = tid & 31;

    if (bx < NAGG1) {
        int w = (bx * 256 + tid) >> 5;
        int c0 = lane * 4;

        float4 xrv = *(const float4*)&g_xr1[w * D1 + c0];
        float4 atv = *(const float4*)&att[c0];

        float a0 = 0.f, a1 = 0.f, a2 = 0.f, a3 = 0.f, dsum = 0.f;
        int beg = g_rowptr[w], end = g_rowptr[w + 1];
        int last = end - 1;

        int s0 = g_csr[beg];
        int s1 = g_csr[beg + 1 <= last ? beg + 1 : last];
        uint32_t c0v = *(const uint32_t*)&g_xl1f8[s0 * D1 + c0];
        uint32_t c1v = *(const uint32_t*)&g_xl1f8[s1 * D1 + c0];

        auto body = [&](uint32_t v) {
            float2 f01 = unpack_e4m3((uint16_t)(v & 0xffffu));
            float2 f23 = unpack_e4m3((uint16_t)(v >> 16));
            float u0 = f01.x + xrv.x; u0 = u0 > 0.f ? u0 : NEG * u0;
            float u1 = f01.y + xrv.y; u1 = u1 > 0.f ? u1 : NEG * u1;
            float u2 = f23.x + xrv.z; u2 = u2 > 0.f ? u2 : NEG * u2;
            float u3 = f23.y + xrv.w; u3 = u3 > 0.f ? u3 : NEG * u3;
            float p = u0 * atv.x + u1 * atv.y + u2 * atv.z + u3 * atv.w;
            p += __shfl_xor_sync(0xffffffffu, p, 1);
            p += __shfl_xor_sync(0xffffffffu, p, 2);
            float ex = __expf(p);
            dsum += ex;
            a0 = fmaf(ex, f01.x, a0);
            a1 = fmaf(ex, f01.y, a1);
            a2 = fmaf(ex, f23.x, a2);
            a3 = fmaf(ex, f23.y, a3);
        };

        for (int i = beg; i < end; i += 2) {
            int j0 = i + 2 <= last ? i + 2 : last;
            int j1 = i + 3 <= last ? i + 3 : last;
            int t0 = g_csr[j0], t1 = g_csr[j1];
            uint32_t n0 = *(const uint32_t*)&g_xl1f8[t0 * D1 + c0];
            uint32_t n1 = *(const uint32_t*)&g_xl1f8[t1 * D1 + c0];
            body(c0v);
            if (i + 1 < end) body(c1v);
            c0v = n0;
            c1v = n1;
        }
        float inv = 1.f / dsum;
        float4 bv = *(const float4*)&bias[c0];
        float o0 = fmaxf(fmaf(a0, inv, bv.x), 0.f);
        float o1 = fmaxf(fmaf(a1, inv, bv.y), 0.f);
        float o2 = fmaxf(fmaf(a2, inv, bv.z), 0.f);
        float o3 = fmaxf(fmaf(a3, inv, bv.w), 0.f);
        uint2 oh;
        *(__nv_bfloat162*)&oh.x = __floats2bfloat162_rn(o0, o1);
        *(__nv_bfloat162*)&oh.y = __floats2bfloat162_rn(o2, o3);
        *(uint2*)&g_x1h[w * D1 + c0] = oh;
    } else {
        int w = ((bx - NAGG1) * 256 + tid) >> 5;
        if (w >= B) return;
        long long a1, a2;
        if (g_flag) { a1 = ((const int*)a1p)[w]; a2 = ((const int*)a2p)[w]; }
        else        { a1 = ((const long long*)a1p)[w]; a2 = ((const long long*)a2p)[w]; }
        const float* v1 = vanilla + a1 * INCH;
        const float* v2 = vanilla + a2 * INCH;
        float acc = 0.f;
#pragma unroll
        for (int j = lane; j < 256; j += 32) {
            acc = fmaf(v1[j], Wc[j],       acc);
            acc = fmaf(v2[j], Wc[256 + j], acc);
        }
#pragma unroll
        for (int off = 16; off > 0; off >>= 1) acc += __shfl_xor_sync(0xffffffffu, acc, off);
        if (lane == 0) g_logv[w] = acc;
    }
}

// ---------------------------------------------------------------------------
// Conv2 aggregation: warp/node; lane = 8 chans; FP8 gathers; 2-edge pipeline.
// ---------------------------------------------------------------------------
__global__ __launch_bounds__(256)
void agg_conv2_kernel(const float* __restrict__ att, const float* __restrict__ bias) {
    int w = (blockIdx.x * blockDim.x + threadIdx.x) >> 5;
    int lane = threadIdx.x & 31;
    if (w >= NNODE) return;
    int c0 = lane * 8;

    float4 xra = *(const float4*)&g_xr2[w * D2 + c0];
    float4 xrb = *(const float4*)&g_xr2[w * D2 + c0 + 4];
    float4 ata = *(const float4*)&att[c0];
    float4 atb = *(const float4*)&att[c0 + 4];
    float xr[8] = {xra.x, xra.y, xra.z, xra.w, xrb.x, xrb.y, xrb.z, xrb.w};
    float at[8] = {ata.x, ata.y, ata.z, ata.w, atb.x, atb.y, atb.z, atb.w};

    float acc[8] = {0.f, 0.f, 0.f, 0.f, 0.f, 0.f, 0.f, 0.f};
    float dsum = 0.f;
    int beg = g_rowptr[w], end = g_rowptr[w + 1];
    int last = end - 1;

    int s0 = g_csr[beg];
    int s1 = g_csr[beg + 1 <= last ? beg + 1 : last];
    uint2 c0v = *(const uint2*)&g_xl2f8[s0 * D2 + c0];
    uint2 c1v = *(const uint2*)&g_xl2f8[s1 * D2 + c0];

    auto body = [&](uint2 cv) {
        float xl[8];
        float2 f;
        f = unpack_e4m3((uint16_t)(cv.x & 0xffffu)); xl[0] = f.x; xl[1] = f.y;
        f = unpack_e4m3((uint16_t)(cv.x >> 16));     xl[2] = f.x; xl[3] = f.y;
        f = unpack_e4m3((uint16_t)(cv.y & 0xffffu)); xl[4] = f.x; xl[5] = f.y;
        f = unpack_e4m3((uint16_t)(cv.y >> 16));     xl[6] = f.x; xl[7] = f.y;
        float p = 0.f;
#pragma unroll
        for (int j = 0; j < 8; j++) {
            float t = xl[j] + xr[j];
            t = t > 0.f ? t : NEG * t;
            p = fmaf(t, at[j], p);
        }
#pragma unroll
        for (int off = 16; off > 0; off >>= 1) p += __shfl_xor_sync(0xffffffffu, p, off);
        float ex = __expf(p);
        dsum += ex;
#pragma unroll
        for (int j = 0; j < 8; j++) acc[j] = fmaf(ex, xl[j], acc[j]);
    };

    for (int i = beg; i < end; i += 2) {
        int j0 = i + 2 <= last ? i + 2 : last;
        int j1 = i + 3 <= last ? i + 3 : last;
        int t0 = g_csr[j0], t1 = g_csr[j1];
        uint2 n0 = *(const uint2*)&g_xl2f8[t0 * D2 + c0];
        uint2 n1 = *(const uint2*)&g_xl2f8[t1 * D2 + c0];
        body(c0v);
        if (i + 1 < end) body(c1v);
        c0v = n0;
        c1v = n1;
    }
    float inv = 1.f / dsum;
    float4 ba = *(const float4*)&bias[c0];
    float4 bb = *(const float4*)&bias[c0 + 4];
    float4 oa, ob;
    oa.x = fmaf(acc[0], inv, ba.x);
    oa.y = fmaf(acc[1], inv, ba.y);
    oa.z = fmaf(acc[2], inv, ba.z);
    oa.w = fmaf(acc[3], inv, ba.w);
    ob.x = fmaf(acc[4], inv, bb.x);
    ob.y = fmaf(acc[5], inv, bb.y);
    ob.z = fmaf(acc[6], inv, bb.z);
    ob.w = fmaf(acc[7], inv, bb.w);
    *(float4*)&g_x2[w * D2 + c0] = oa;
    *(float4*)&g_x2[w * D2 + c0 + 4] = ob;
}

// ---------------------------------------------------------------------------
// Classifier tail: add GNN terms to precomputed vanilla partial.
// ---------------------------------------------------------------------------
__global__ __launch_bounds__(256)
void classify_kernel(const void* a1p, const void* a2p,
                     const float* __restrict__ Wc, const float* __restrict__ bc,
                     float* __restrict__ out, int B) {
    int w = (blockIdx.x * blockDim.x + threadIdx.x) >> 5;
    int lane = threadIdx.x & 31;
    if (w >= B) return;
    long long a1, a2;
    if (g_flag) { a1 = ((const int*)a1p)[w]; a2 = ((const int*)a2p)[w]; }
    else        { a1 = ((const long long*)a1p)[w]; a2 = ((const long long*)a2p)[w]; }

    const float* x1 = g_x2 + a1 * D2;
    const float* x2 = g_x2 + a2 * D2;

    float acc = 0.f;
#pragma unroll
    for (int j = lane; j < 256; j += 32) {
        acc = fmaf(x1[j], Wc[512 + j], acc);
        acc = fmaf(x2[j], Wc[768 + j], acc);
    }
#pragma unroll
    for (int off = 16; off > 0; off >>= 1) acc += __shfl_xor_sync(0xffffffffu, acc, off);
    if (lane == 0) out[w] = acc + g_logv[w] + bc[0];
}

// ---------------------------------------------------------------------------
// Launch
// ---------------------------------------------------------------------------
extern "C" void kernel_launch(void* const* d_in, const int* in_sizes, int n_in,
                              void* d_out, int out_size) {
    const float* gnn_x   = (const float*)d_in[0];
    const float* vanilla = (const float*)d_in[1];
    const int*   e_src   = (const int*)d_in[2];
    const int*   e_dst   = (const int*)d_in[3];
    const void*  a1p     = d_in[4];
    const void*  a2p     = d_in[5];
    const float* Wl1     = (const float*)d_in[6];
    const float* Wr1     = (const float*)d_in[8];
    const float* att1    = (const float*)d_in[10];
    const float* bias1   = (const float*)d_in[11];
    const float* Wl2     = (const float*)d_in[12];
    const float* Wr2     = (const float*)d_in[14];
    const float* att2    = (const float*)d_in[16];
    const float* bias2   = (const float*)d_in[17];
    const float* Wc      = (const float*)d_in[18];
    const float* bc      = (const float*)d_in[19];

    const int E = in_sizes[2];
    const int Etot = E + NNODE;
    const int B = in_sizes[4];
    float* out = (float*)d_out;

    __nv_bfloat16 *p_xh, *p_w1b, *p_w2b, *p_x1h;
    uint8_t *p_xl1f8, *p_xl2f8;
    float *p_xr1, *p_xr2;
    cudaGetSymbolAddress((void**)&p_xh,    g_xh);
    cudaGetSymbolAddress((void**)&p_w1b,   g_w1b);
    cudaGetSymbolAddress((void**)&p_w2b,   g_w2b);
    cudaGetSymbolAddress((void**)&p_xl1f8, g_xl1f8);
    cudaGetSymbolAddress((void**)&p_xr1,   g_xr1);
    cudaGetSymbolAddress((void**)&p_x1h,   g_x1h);
    cudaGetSymbolAddress((void**)&p_xl2f8, g_xl2f8);
    cudaGetSymbolAddress((void**)&p_xr2,   g_xr2);

    constexpr int SMEM_GEMM = 4 * 2 * 128 * 40 * 2;   // 81920 B (4 stages)
    cudaFuncSetAttribute(g1_scatter_kernel,
                         cudaFuncAttributeMaxDynamicSharedMemorySize, SMEM_GEMM);
    cudaFuncSetAttribute(gemm2_kernel,
                         cudaFuncAttributeMaxDynamicSharedMemorySize, SMEM_GEMM);

    // ---- 1. init ----
    init_kernel<<<ceil_div(NNODE, 256), 256>>>();

    // ---- 2. fused pre-pass ----
    int nbX = ceil_div(NNODE * INCH / 4, 256);
    int nbW = ceil_div(4 * 32768, 256);
    int nbC = ceil_div(E, 256);
    int nbD = ceil_div(B / 2, 256);
    pre_kernel<<<nbX + nbW + nbC + nbD, 256>>>(
        gnn_x, p_xh, Wl1, Wr1, Wl2, Wr2, p_w1b, p_w2b,
        e_dst, E, a1p, a2p, B, nbX, nbW, nbC);

    // ---- 3. chained scan ----
    scan_chained_kernel<<<ceil_div(NNODE, 1024), 256>>>();

    // ---- 4. fused GEMM1 + scatter ----
    int nGemm1 = 2 * ceil_div(NNODE, 128);           // 314
    int nScat  = ceil_div(Etot, 1024);
    g1_scatter_kernel<<<nGemm1 + nScat, 256, SMEM_GEMM>>>(
        p_xh, p_w1b, p_xl1f8, p_xr1, e_src, e_dst, E, Etot, nGemm1);

    // ---- 5. conv1 aggregation + vanilla-classifier partial ----
    int nClsV = ceil_div(B * 32, 256);
    agg1_clsv_kernel<<<NAGG1 + nClsV, 256>>>(att1, bias1, vanilla, a1p, a2p, Wc, B);

    // ---- 6. GEMM2 ----
    gemm2_kernel<<<4 * ceil_div(NNODE, 128), 256, SMEM_GEMM>>>(
        p_x1h, p_w2b, p_xl2f8, p_xr2);

    // ---- 7. conv2 aggregation ----
    agg_conv2_kernel<<<ceil_div(NNODE * 32, 256), 256>>>(att2, bias2);

    // ---- 8. classifier tail ----
    classify_kernel<<<ceil_div(B * 32, 256), 256>>>(a1p, a2p, Wc, bc, out, B);
}

// round 17
// speedup vs baseline: 1.0319x; 1.0088x over previous
#include <cuda_runtime.h>
#include <cuda_bf16.h>
#include <cuda_fp16.h>
#include <cstdint>

// ---------------------------------------------------------------------------
// Problem constants
// ---------------------------------------------------------------------------
static constexpr int NNODE = 20000;
static constexpr int EMAX  = 640000;
static constexpr int ETOT  = EMAX + NNODE;
static constexpr int INCH  = 256;
static constexpr int D1    = 128;            // conv1 out (8 heads x 16)
static constexpr int D2    = 256;            // conv2 out (1 head x 256)
static constexpr float NEG = 0.2f;
static constexpr int NAGG1 = NNODE * 32 / 256;      // 2500 agg1 blocks

// ---------------------------------------------------------------------------
// Scratch (__device__ globals; no allocation allowed)
// ---------------------------------------------------------------------------
__device__ __nv_bfloat16 g_xh  [NNODE * INCH];   // gnn_x bf16 (GEMM1 A)
__device__ __nv_bfloat16 g_w1b [2 * D1 * INCH];  // [Wl1^T ; Wr1^T] bf16
__device__ __nv_bfloat16 g_w2b [2 * D2 * D1];    // [Wl2^T ; Wr2^T] bf16
__device__ uint8_t       g_xl1f8[NNODE * D1];    // conv1 xl (e4m3, gathered)
__device__ float         g_xr1 [NNODE * D1];     // conv1 xr (fp32)
__device__ __nv_bfloat16 g_x1h [NNODE * D1];     // relu(conv1 out) bf16
__device__ uint8_t       g_xl2f8[NNODE * D2];    // conv2 xl (e4m3, gathered)
__device__ float         g_xr2 [NNODE * D2];     // conv2 xr (fp32)
__device__ float         g_x2  [NNODE * D2];     // conv2 out (fp32)
__device__ float         g_logv[8192];           // vanilla part of classifier
__device__ int   g_counts[NNODE];
__device__ int   g_rank  [EMAX];                 // rank of edge within its dst
__device__ int   g_rowptr[NNODE + 1];
__device__ int   g_csr[ETOT];
__device__ int   g_bsum[32];
__device__ int   g_bflag[32];
__device__ int   g_flag;

static inline int ceil_div(int a, int b) { return (a + b - 1) / b; }

// ---------------------------------------------------------------------------
// FP8 (e4m3) pack/unpack — baseline PTX since sm_89, OK on plain sm_103.
// ---------------------------------------------------------------------------
__device__ __forceinline__ uint16_t pack_e4m3(float hi, float lo) {
    uint16_t r;
    asm("cvt.rn.satfinite.e4m3x2.f32 %0, %1, %2;" : "=h"(r) : "f"(hi), "f"(lo));
    return r;
}
__device__ __forceinline__ float2 unpack_e4m3(uint16_t v) {
    uint32_t h2;
    asm("cvt.rn.f16x2.e4m3x2 %0, %1;" : "=r"(h2) : "h"(v));
    return __half22float2(*(__half2*)&h2);
}

// ---------------------------------------------------------------------------
// Init
// ---------------------------------------------------------------------------
__global__ void init_kernel() {
    int i = blockIdx.x * blockDim.x + threadIdx.x;
    if (i < NNODE) g_counts[i] = 0;
    if (i < 32) g_bflag[i] = 0;
    if (i == 0) g_flag = 0;
}

// ---------------------------------------------------------------------------
// Fused pre-pass: bf16 conversions + degree count (captures ranks) + detect.
// ---------------------------------------------------------------------------
__global__ void __launch_bounds__(256)
pre_kernel(const float* __restrict__ x, __nv_bfloat16* __restrict__ xh,
           const float* __restrict__ Wl1, const float* __restrict__ Wr1,
           const float* __restrict__ Wl2, const float* __restrict__ Wr2,
           __nv_bfloat16* __restrict__ w1b, __nv_bfloat16* __restrict__ w2b,
           const int* __restrict__ dst, int E,
           const void* a1p, const void* a2p, int B,
           int nbX, int nbW, int nbC) {
    int bx = blockIdx.x, tid = threadIdx.x;
    if (bx < nbX) {
        int i = bx * 256 + tid;
        constexpr int n4 = NNODE * INCH / 4;
        if (i < n4) {
            float4 v = ((const float4*)x)[i];
            uint2 p;
            *(__nv_bfloat162*)&p.x = __floats2bfloat162_rn(v.x, v.y);
            *(__nv_bfloat162*)&p.y = __floats2bfloat162_rn(v.z, v.w);
            ((uint2*)xh)[i] = p;
        }
    } else if (bx < nbX + nbW) {
        int idx = (bx - nbX) * 256 + tid;
        if (idx < 4 * 32768) {
            int z = idx >> 15, local = idx & 32767;
            const float* W = (z == 0) ? Wl1 : (z == 1) ? Wr1 : (z == 2) ? Wl2 : Wr2;
            __nv_bfloat16* o = (z == 0) ? w1b : (z == 1) ? (w1b + 32768)
                              : (z == 2) ? w2b : (w2b + 32768);
            int K = (z < 2) ? INCH : D1;
            int N = (z < 2) ? D1 : D2;
            int k = local / N, n = local % N;        // consecutive n -> coalesced read
            o[n * K + k] = __float2bfloat16(W[local]);
        }
    } else if (bx < nbX + nbW + nbC) {
        int e = (bx - nbX - nbW) * 256 + tid;
        if (e < E) g_rank[e] = atomicAdd(&g_counts[dst[e]], 1);
    } else {
        int i = (bx - nbX - nbW - nbC) * 256 + tid;
        if (i < B / 2) {
            long long v1 = ((const long long*)a1p)[i];
            long long v2 = ((const long long*)a2p)[i];
            if (v1 < 0 || v1 >= NNODE || v2 < 0 || v2 >= NNODE) g_flag = 1;
        }
    }
}

// ---------------------------------------------------------------------------
// Chained multi-block scan over (counts[i] + 1). 20 co-resident blocks,
// 256 threads x 4 nodes each.
// ---------------------------------------------------------------------------
__global__ void __launch_bounds__(256)
scan_chained_kernel() {
    __shared__ int sh[256];
    __shared__ int s_off;
    int tid = threadIdx.x, bx = blockIdx.x;
    int base = bx * 1024 + tid * 4;
    int v0 = (base + 0 < NNODE) ? g_counts[base + 0] + 1 : 0;
    int v1 = (base + 1 < NNODE) ? g_counts[base + 1] + 1 : 0;
    int v2 = (base + 2 < NNODE) ? g_counts[base + 2] + 1 : 0;
    int v3 = (base + 3 < NNODE) ? g_counts[base + 3] + 1 : 0;
    int s4 = v0 + v1 + v2 + v3;
    sh[tid] = s4;
    __syncthreads();
    for (int off = 1; off < 256; off <<= 1) {
        int t = (tid >= off) ? sh[tid - off] : 0;
        __syncthreads();
        sh[tid] += t;
        __syncthreads();
    }
    int incl = sh[tid];
    if (tid == 0) {
        int off = 0;
        if (bx > 0) {
            while (atomicAdd(&g_bflag[bx - 1], 0) == 0) { }
            off = atomicAdd(&g_bsum[bx - 1], 0);
        }
        s_off = off;
        atomicExch(&g_bsum[bx], off + sh[255]);
        __threadfence();
        atomicExch(&g_bflag[bx], 1);
    }
    __syncthreads();
    int r = s_off + incl - s4;
    if (base + 0 < NNODE) { r += v0; g_rowptr[base + 1] = r; }
    if (base + 1 < NNODE) { r += v1; g_rowptr[base + 2] = r; }
    if (base + 2 < NNODE) { r += v2; g_rowptr[base + 3] = r; }
    if (base + 3 < NNODE) { r += v3; g_rowptr[base + 4] = r; }
    if (bx == 0 && tid == 0) g_rowptr[0] = 0;
}

// ---------------------------------------------------------------------------
// 3-stage cp.async bf16 HMMA GEMM body, block tile 128x64, warp tile 32x32.
// 8 warps (4 row x 2 col). acc = 32 regs/thread -> 3 CTAs/SM (24 warps).
// xl output written as FP8 (e4m3); xr output fp32.
// ---------------------------------------------------------------------------
template<int KD, int ND>
__device__ __forceinline__ void gemm_body(
    int rowTile, int slab,
    const __nv_bfloat16* __restrict__ A,
    const __nv_bfloat16* __restrict__ Wt,
    uint8_t* __restrict__ outLf8,
    float* __restrict__ outRf,
    char* smem)
{
    constexpr int STR    = 40;
    constexpr int NT     = KD / 32;
    constexpr int ABYTES = 128 * STR * 2;      // 10240
    constexpr int BBYTES = 64 * STR * 2;       // 5120
    constexpr int SBYTES = ABYTES + BBYTES;    // 15360
    constexpr int NSTAGE = 3;

    int tid = threadIdx.x, lane = tid & 31, wid = tid >> 5;
    int warpRow = wid >> 1, warpCol = wid & 1;    // 4x2 warp grid
    int g = lane >> 2, t4 = lane & 3;
    int base = rowTile * 128;
    int slabBase = slab * 64;

    uint32_t sbase;
    asm("{ .reg .u64 t; cvta.to.shared.u64 t, %1; cvt.u32.u64 %0, t; }"
        : "=r"(sbase) : "l"(smem));

    int am = lane >> 3, ari = lane & 7;
    int bm = (lane >> 3) & 1, bri = lane & 7;
    uint32_t aoff[2], boff[4];
#pragma unroll
    for (int ma = 0; ma < 2; ma++)
        aoff[ma] = ((warpRow * 32 + ma * 16 + (am & 1) * 8 + ari) * STR + (am >> 1) * 8) * 2;
#pragma unroll
    for (int na = 0; na < 4; na++)
        boff[na] = ((warpCol * 32 + na * 8 + bri) * STR + bm * 8) * 2;

    float acc[2][4][4];
#pragma unroll
    for (int i = 0; i < 2; i++)
#pragma unroll
        for (int j = 0; j < 4; j++)
#pragma unroll
            for (int q = 0; q < 4; q++) acc[i][j][q] = 0.f;

    auto issue = [&](int s, int kt) {
        // A tile: 128 rows x 32 halves = 512 16B-chunks
#pragma unroll
        for (int it = 0; it < 2; it++) {
            int chunk = tid + it * 256;
            int r = chunk >> 2, c4 = chunk & 3;
            int gr = base + r;
            int grs = (gr < NNODE) ? gr : 0;
            uint32_t da = sbase + s * SBYTES + (r * STR + c4 * 8) * 2;
            const void* sa = &A[(size_t)grs * KD + kt * 32 + c4 * 8];
            int sz = (gr < NNODE) ? 16 : 0;
            asm volatile("cp.async.cg.shared.global [%0], [%1], 16, %2;"
                         :: "r"(da), "l"(sa), "r"(sz));
        }
        // B tile: 64 rows x 32 halves = 256 16B-chunks
        {
            int r = tid >> 2, c4 = tid & 3;
            uint32_t db = sbase + s * SBYTES + ABYTES + (r * STR + c4 * 8) * 2;
            const void* sb = &Wt[(size_t)(slabBase + r) * KD + kt * 32 + c4 * 8];
            asm volatile("cp.async.cg.shared.global [%0], [%1], 16;"
                         :: "r"(db), "l"(sb));
        }
        asm volatile("cp.async.commit_group;" ::: "memory");
    };

#pragma unroll
    for (int s = 0; s < NSTAGE - 1; s++)
        if (s < NT) issue(s, s); else asm volatile("cp.async.commit_group;" ::: "memory");

    for (int kt = 0; kt < NT; kt++) {
        asm volatile("cp.async.wait_group %0;" :: "n"(NSTAGE - 2) : "memory");
        __syncthreads();
        if (kt + NSTAGE - 1 < NT) issue((kt + NSTAGE - 1) % NSTAGE, kt + NSTAGE - 1);
        else asm volatile("cp.async.commit_group;" ::: "memory");

        uint32_t sA = sbase + (kt % NSTAGE) * SBYTES;
        uint32_t sB = sA + ABYTES;
#pragma unroll
        for (int kc = 0; kc < 2; kc++) {
            uint32_t a[2][4], b[4][2];
#pragma unroll
            for (int ma = 0; ma < 2; ma++) {
                asm volatile("ldmatrix.sync.aligned.m8n8.x4.shared.b16 "
                             "{%0, %1, %2, %3}, [%4];"
                             : "=r"(a[ma][0]), "=r"(a[ma][1]),
                               "=r"(a[ma][2]), "=r"(a[ma][3])
                             : "r"(sA + aoff[ma] + kc * 32));
            }
#pragma unroll
            for (int na = 0; na < 4; na++) {
                asm volatile("ldmatrix.sync.aligned.m8n8.x2.shared.b16 "
                             "{%0, %1}, [%2];"
                             : "=r"(b[na][0]), "=r"(b[na][1])
                             : "r"(sB + boff[na] + kc * 32));
            }
#pragma unroll
            for (int ma = 0; ma < 2; ma++)
#pragma unroll
                for (int na = 0; na < 4; na++) {
                    asm volatile(
                        "mma.sync.aligned.m16n8k16.row.col.f32.bf16.bf16.f32 "
                        "{%0, %1, %2, %3}, {%4, %5, %6, %7}, {%8, %9}, {%0, %1, %2, %3};"
                        : "+f"(acc[ma][na][0]), "+f"(acc[ma][na][1]),
                          "+f"(acc[ma][na][2]), "+f"(acc[ma][na][3])
                        : "r"(a[ma][0]), "r"(a[ma][1]), "r"(a[ma][2]), "r"(a[ma][3]),
                          "r"(b[na][0]), "r"(b[na][1]));
                }
        }
        __syncthreads();
    }

    bool isL = slabBase < ND;
    int colSlab = isL ? slabBase : (slabBase - ND);
#pragma unroll
    for (int ma = 0; ma < 2; ma++) {
        int r0 = base + warpRow * 32 + ma * 16 + g;
#pragma unroll
        for (int na = 0; na < 4; na++) {
            int col = colSlab + warpCol * 32 + na * 8 + 2 * t4;
            if (isL) {
                uint16_t e0 = pack_e4m3(acc[ma][na][1], acc[ma][na][0]);
                uint16_t e1 = pack_e4m3(acc[ma][na][3], acc[ma][na][2]);
                if (r0 < NNODE)     *(uint16_t*)&outLf8[(size_t)r0 * ND + col] = e0;
                if (r0 + 8 < NNODE) *(uint16_t*)&outLf8[(size_t)(r0 + 8) * ND + col] = e1;
            } else {
                if (r0 < NNODE)
                    *(float2*)&outRf[(size_t)r0 * ND + col] =
                        make_float2(acc[ma][na][0], acc[ma][na][1]);
                if (r0 + 8 < NNODE)
                    *(float2*)&outRf[(size_t)(r0 + 8) * ND + col] =
                        make_float2(acc[ma][na][2], acc[ma][na][3]);
            }
        }
    }
}

// ---------------------------------------------------------------------------
// Fused GEMM1 + atomic-free scatter (ranks precomputed).
// GEMM1: 4 slabs of 64 cols per row tile.
// ---------------------------------------------------------------------------
__global__ void __launch_bounds__(256, 3)
g1_scatter_kernel(const __nv_bfloat16* __restrict__ A,
                  const __nv_bfloat16* __restrict__ Wt,
                  uint8_t* __restrict__ outLf8, float* __restrict__ outRf,
                  const int* __restrict__ src, const int* __restrict__ dst,
                  int E, int Etot, int nGemm) {
    extern __shared__ char smem[];
    if ((int)blockIdx.x < nGemm) {
        gemm_body<INCH, D1>(blockIdx.x >> 2, blockIdx.x & 3, A, Wt, outLf8, outRf, smem);
    } else {
        int b = blockIdx.x - nGemm;
#pragma unroll
        for (int q = 0; q < 4; q++) {
            int e = (b * 4 + q) * 256 + threadIdx.x;
            if (e < Etot) {
                if (e < E) {
                    int d = dst[e];
                    g_csr[g_rowptr[d] + g_rank[e]] = src[e];
                } else {
                    int i = e - E;
                    g_csr[g_rowptr[i] + g_counts[i]] = i;
                }
            }
        }
    }
}

__global__ void __launch_bounds__(256, 3)
gemm2_kernel(const __nv_bfloat16* __restrict__ A,
             const __nv_bfloat16* __restrict__ Wt,
             uint8_t* __restrict__ outLf8, float* __restrict__ outRf) {
    extern __shared__ char smem[];
    gemm_body<D1, D2>(blockIdx.x >> 3, blockIdx.x & 7, A, Wt, outLf8, outRf, smem);
}

// ---------------------------------------------------------------------------
// Conv1 aggregation + vanilla-classifier partial (independent, same footprint).
// ---------------------------------------------------------------------------
__global__ __launch_bounds__(256)
void agg1_clsv_kernel(const float* __restrict__ att, const float* __restrict__ bias,
                      const float* __restrict__ vanilla,
                      const void* a1p, const void* a2p,
                      const float* __restrict__ Wc, int B) {
    int bx = blockIdx.x, tid = threadIdx.x;
    int lane = tid & 31;

    if (bx < NAGG1) {
        int w = (bx * 256 + tid) >> 5;
        int c0 = lane * 4;

        float4 xrv = *(const float4*)&g_xr1[w * D1 + c0];
        float4 atv = *(const float4*)&att[c0];

        float a0 = 0.f, a1 = 0.f, a2 = 0.f, a3 = 0.f, dsum = 0.f;
        int beg = g_rowptr[w], end = g_rowptr[w + 1];
        int last = end - 1;

        int s0 = g_csr[beg];
        int s1 = g_csr[beg + 1 <= last ? beg + 1 : last];
        uint32_t c0v = *(const uint32_t*)&g_xl1f8[s0 * D1 + c0];
        uint32_t c1v = *(const uint32_t*)&g_xl1f8[s1 * D1 + c0];

        auto body = [&](uint32_t v) {
            float2 f01 = unpack_e4m3((uint16_t)(v & 0xffffu));
            float2 f23 = unpack_e4m3((uint16_t)(v >> 16));
            float u0 = f01.x + xrv.x; u0 = u0 > 0.f ? u0 : NEG * u0;
            float u1 = f01.y + xrv.y; u1 = u1 > 0.f ? u1 : NEG * u1;
            float u2 = f23.x + xrv.z; u2 = u2 > 0.f ? u2 : NEG * u2;
            float u3 = f23.y + xrv.w; u3 = u3 > 0.f ? u3 : NEG * u3;
            float p = u0 * atv.x + u1 * atv.y + u2 * atv.z + u3 * atv.w;
            p += __shfl_xor_sync(0xffffffffu, p, 1);
            p += __shfl_xor_sync(0xffffffffu, p, 2);
            float ex = __expf(p);
            dsum += ex;
            a0 = fmaf(ex, f01.x, a0);
            a1 = fmaf(ex, f01.y, a1);
            a2 = fmaf(ex, f23.x, a2);
            a3 = fmaf(ex, f23.y, a3);
        };

        for (int i = beg; i < end; i += 2) {
            int j0 = i + 2 <= last ? i + 2 : last;
            int j1 = i + 3 <= last ? i + 3 : last;
            int t0 = g_csr[j0], t1 = g_csr[j1];
            uint32_t n0 = *(const uint32_t*)&g_xl1f8[t0 * D1 + c0];
            uint32_t n1 = *(const uint32_t*)&g_xl1f8[t1 * D1 + c0];
            body(c0v);
            if (i + 1 < end) body(c1v);
            c0v = n0;
            c1v = n1;
        }
        float inv = 1.f / dsum;
        float4 bv = *(const float4*)&bias[c0];
        float o0 = fmaxf(fmaf(a0, inv, bv.x), 0.f);
        float o1 = fmaxf(fmaf(a1, inv, bv.y), 0.f);
        float o2 = fmaxf(fmaf(a2, inv, bv.z), 0.f);
        float o3 = fmaxf(fmaf(a3, inv, bv.w), 0.f);
        uint2 oh;
        *(__nv_bfloat162*)&oh.x = __floats2bfloat162_rn(o0, o1);
        *(__nv_bfloat162*)&oh.y = __floats2bfloat162_rn(o2, o3);
        *(uint2*)&g_x1h[w * D1 + c0] = oh;
    } else {
        int w = ((bx - NAGG1) * 256 + tid) >> 5;
        if (w >= B) return;
        long long a1, a2;
        if (g_flag) { a1 = ((const int*)a1p)[w]; a2 = ((const int*)a2p)[w]; }
        else        { a1 = ((const long long*)a1p)[w]; a2 = ((const long long*)a2p)[w]; }
        const float* v1 = vanilla + a1 * INCH;
        const float* v2 = vanilla + a2 * INCH;
        float acc = 0.f;
#pragma unroll
        for (int j = lane; j < 256; j += 32) {
            acc = fmaf(v1[j], Wc[j],       acc);
            acc = fmaf(v2[j], Wc[256 + j], acc);
        }
#pragma unroll
        for (int off = 16; off > 0; off >>= 1) acc += __shfl_xor_sync(0xffffffffu, acc, off);
        if (lane == 0) g_logv[w] = acc;
    }
}

// ---------------------------------------------------------------------------
// Conv2 aggregation: warp/node; lane = 8 chans; FP8 gathers; 2-edge pipeline.
// ---------------------------------------------------------------------------
__global__ __launch_bounds__(256)
void agg_conv2_kernel(const float* __restrict__ att, const float* __restrict__ bias) {
    int w = (blockIdx.x * blockDim.x + threadIdx.x) >> 5;
    int lane = threadIdx.x & 31;
    if (w >= NNODE) return;
    int c0 = lane * 8;

    float4 xra = *(const float4*)&g_xr2[w * D2 + c0];
    float4 xrb = *(const float4*)&g_xr2[w * D2 + c0 + 4];
    float4 ata = *(const float4*)&att[c0];
    float4 atb = *(const float4*)&att[c0 + 4];
    float xr[8] = {xra.x, xra.y, xra.z, xra.w, xrb.x, xrb.y, xrb.z, xrb.w};
    float at[8] = {ata.x, ata.y, ata.z, ata.w, atb.x, atb.y, atb.z, atb.w};

    float acc[8] = {0.f, 0.f, 0.f, 0.f, 0.f, 0.f, 0.f, 0.f};
    float dsum = 0.f;
    int beg = g_rowptr[w], end = g_rowptr[w + 1];
    int last = end - 1;

    int s0 = g_csr[beg];
    int s1 = g_csr[beg + 1 <= last ? beg + 1 : last];
    uint2 c0v = *(const uint2*)&g_xl2f8[s0 * D2 + c0];
    uint2 c1v = *(const uint2*)&g_xl2f8[s1 * D2 + c0];

    auto body = [&](uint2 cv) {
        float xl[8];
        float2 f;
        f = unpack_e4m3((uint16_t)(cv.x & 0xffffu)); xl[0] = f.x; xl[1] = f.y;
        f = unpack_e4m3((uint16_t)(cv.x >> 16));     xl[2] = f.x; xl[3] = f.y;
        f = unpack_e4m3((uint16_t)(cv.y & 0xffffu)); xl[4] = f.x; xl[5] = f.y;
        f = unpack_e4m3((uint16_t)(cv.y >> 16));     xl[6] = f.x; xl[7] = f.y;
        float p = 0.f;
#pragma unroll
        for (int j = 0; j < 8; j++) {
            float t = xl[j] + xr[j];
            t = t > 0.f ? t : NEG * t;
            p = fmaf(t, at[j], p);
        }
#pragma unroll
        for (int off = 16; off > 0; off >>= 1) p += __shfl_xor_sync(0xffffffffu, p, off);
        float ex = __expf(p);
        dsum += ex;
#pragma unroll
        for (int j = 0; j < 8; j++) acc[j] = fmaf(ex, xl[j], acc[j]);
    };

    for (int i = beg; i < end; i += 2) {
        int j0 = i + 2 <= last ? i + 2 : last;
        int j1 = i + 3 <= last ? i + 3 : last;
        int t0 = g_csr[j0], t1 = g_csr[j1];
        uint2 n0 = *(const uint2*)&g_xl2f8[t0 * D2 + c0];
        uint2 n1 = *(const uint2*)&g_xl2f8[t1 * D2 + c0];
        body(c0v);
        if (i + 1 < end) body(c1v);
        c0v = n0;
        c1v = n1;
    }
    float inv = 1.f / dsum;
    float4 ba = *(const float4*)&bias[c0];
    float4 bb = *(const float4*)&bias[c0 + 4];
    float4 oa, ob;
    oa.x = fmaf(acc[0], inv, ba.x);
    oa.y = fmaf(acc[1], inv, ba.y);
    oa.z = fmaf(acc[2], inv, ba.z);
    oa.w = fmaf(acc[3], inv, ba.w);
    ob.x = fmaf(acc[4], inv, bb.x);
    ob.y = fmaf(acc[5], inv, bb.y);
    ob.z = fmaf(acc[6], inv, bb.z);
    ob.w = fmaf(acc[7], inv, bb.w);
    *(float4*)&g_x2[w * D2 + c0] = oa;
    *(float4*)&g_x2[w * D2 + c0 + 4] = ob;
}

// ---------------------------------------------------------------------------
// Classifier tail: add GNN terms to precomputed vanilla partial.
// ---------------------------------------------------------------------------
__global__ __launch_bounds__(256)
void classify_kernel(const void* a1p, const void* a2p,
                     const float* __restrict__ Wc, const float* __restrict__ bc,
                     float* __restrict__ out, int B) {
    int w = (blockIdx.x * blockDim.x + threadIdx.x) >> 5;
    int lane = threadIdx.x & 31;
    if (w >= B) return;
    long long a1, a2;
    if (g_flag) { a1 = ((const int*)a1p)[w]; a2 = ((const int*)a2p)[w]; }
    else        { a1 = ((const long long*)a1p)[w]; a2 = ((const long long*)a2p)[w]; }

    const float* x1 = g_x2 + a1 * D2;
    const float* x2 = g_x2 + a2 * D2;

    float acc = 0.f;
#pragma unroll
    for (int j = lane; j < 256; j += 32) {
        acc = fmaf(x1[j], Wc[512 + j], acc);
        acc = fmaf(x2[j], Wc[768 + j], acc);
    }
#pragma unroll
    for (int off = 16; off > 0; off >>= 1) acc += __shfl_xor_sync(0xffffffffu, acc, off);
    if (lane == 0) out[w] = acc + g_logv[w] + bc[0];
}

// ---------------------------------------------------------------------------
// Launch
// ---------------------------------------------------------------------------
extern "C" void kernel_launch(void* const* d_in, const int* in_sizes, int n_in,
                              void* d_out, int out_size) {
    const float* gnn_x   = (const float*)d_in[0];
    const float* vanilla = (const float*)d_in[1];
    const int*   e_src   = (const int*)d_in[2];
    const int*   e_dst   = (const int*)d_in[3];
    const void*  a1p     = d_in[4];
    const void*  a2p     = d_in[5];
    const float* Wl1     = (const float*)d_in[6];
    const float* Wr1     = (const float*)d_in[8];
    const float* att1    = (const float*)d_in[10];
    const float* bias1   = (const float*)d_in[11];
    const float* Wl2     = (const float*)d_in[12];
    const float* Wr2     = (const float*)d_in[14];
    const float* att2    = (const float*)d_in[16];
    const float* bias2   = (const float*)d_in[17];
    const float* Wc      = (const float*)d_in[18];
    const float* bc      = (const float*)d_in[19];

    const int E = in_sizes[2];
    const int Etot = E + NNODE;
    const int B = in_sizes[4];
    float* out = (float*)d_out;

    __nv_bfloat16 *p_xh, *p_w1b, *p_w2b, *p_x1h;
    uint8_t *p_xl1f8, *p_xl2f8;
    float *p_xr1, *p_xr2;
    cudaGetSymbolAddress((void**)&p_xh,    g_xh);
    cudaGetSymbolAddress((void**)&p_w1b,   g_w1b);
    cudaGetSymbolAddress((void**)&p_w2b,   g_w2b);
    cudaGetSymbolAddress((void**)&p_xl1f8, g_xl1f8);
    cudaGetSymbolAddress((void**)&p_xr1,   g_xr1);
    cudaGetSymbolAddress((void**)&p_x1h,   g_x1h);
    cudaGetSymbolAddress((void**)&p_xl2f8, g_xl2f8);
    cudaGetSymbolAddress((void**)&p_xr2,   g_xr2);

    constexpr int SMEM_GEMM = 3 * (128 + 64) * 40 * 2;   // 46080 B (3 stages)
    cudaFuncSetAttribute(g1_scatter_kernel,
                         cudaFuncAttributeMaxDynamicSharedMemorySize, SMEM_GEMM);
    cudaFuncSetAttribute(gemm2_kernel,
                         cudaFuncAttributeMaxDynamicSharedMemorySize, SMEM_GEMM);

    // ---- 1. init ----
    init_kernel<<<ceil_div(NNODE, 256), 256>>>();

    // ---- 2. fused pre-pass ----
    int nbX = ceil_div(NNODE * INCH / 4, 256);
    int nbW = ceil_div(4 * 32768, 256);
    int nbC = ceil_div(E, 256);
    int nbD = ceil_div(B / 2, 256);
    pre_kernel<<<nbX + nbW + nbC + nbD, 256>>>(
        gnn_x, p_xh, Wl1, Wr1, Wl2, Wr2, p_w1b, p_w2b,
        e_dst, E, a1p, a2p, B, nbX, nbW, nbC);

    // ---- 3. chained scan ----
    scan_chained_kernel<<<ceil_div(NNODE, 1024), 256>>>();

    // ---- 4. fused GEMM1 + scatter (64-col slabs: 4 per row tile) ----
    int nGemm1 = 4 * ceil_div(NNODE, 128);           // 628
    int nScat  = ceil_div(Etot, 1024);
    g1_scatter_kernel<<<nGemm1 + nScat, 256, SMEM_GEMM>>>(
        p_xh, p_w1b, p_xl1f8, p_xr1, e_src, e_dst, E, Etot, nGemm1);

    // ---- 5. conv1 aggregation + vanilla-classifier partial ----
    int nClsV = ceil_div(B * 32, 256);
    agg1_clsv_kernel<<<NAGG1 + nClsV, 256>>>(att1, bias1, vanilla, a1p, a2p, Wc, B);

    // ---- 6. GEMM2 (8 slabs of 64 cols) ----
    gemm2_kernel<<<8 * ceil_div(NNODE, 128), 256, SMEM_GEMM>>>(
        p_x1h, p_w2b, p_xl2f8, p_xr2);

    // ---- 7. conv2 aggregation ----
    agg_conv2_kernel<<<ceil_div(NNODE * 32, 256), 256>>>(att2, bias2);

    // ---- 8. classifier tail ----
    classify_kernel<<<ceil_div(B * 32, 256), 256>>>(a1p, a2p, Wc, bc, out, B);
}